// round 13
// baseline (speedup 1.0000x reference)
#include <cuda_runtime.h>
#include <cstdint>

// Unfold (im2col): x[32,64,64,64] f32, 3x3/s1 -> out[32,576,3844] f32
// out[(bc*9+3ki+kj)][l+e] = ch[ki*64 + kj + (l+e) + 2*floor((l+e)/62)]
//
// R13: R10's padded-smem shared-window gather (8 LDS + 6 SEL per (m,ki),
// conflict-free) but rows are assembled in smem and stored by TMA
// (cp.async.bulk), removing the 3x STG.128 (12 cyc issue each!) from the
// LSU: per warp-(32m,ki) issue cost drops 52 -> 28 cyc. Double-buffered
// 3-row groups overlap TMA drain with the next group's assembly.

#define HW     64
#define CH     4096
#define WO     62
#define L      3844
#define NV4    961                 // float4 per output row
#define SMW    4240                // padded input: 4096 + pad + slack
#define NT     512
#define GRPF   (3 * L)             // floats per 3-row group buffer = 11532
#define SMEMB  ((SMW + 2 * GRPF) * 4)   // 109216 bytes

__device__ __forceinline__ int PADI(int w) { return w + (w >> 5); }

__device__ __forceinline__ uint32_t smem_u32(const void* p) {
    uint32_t a;
    asm("{ .reg .u64 t; cvta.to.shared.u64 t, %1; cvt.u32.u64 %0, t; }"
        : "=r"(a) : "l"(p));
    return a;
}

__global__ __launch_bounds__(NT, 2)
void unfold_kernel(const float* __restrict__ x, float* __restrict__ out)
{
    extern __shared__ float smem[];
    float* sin  = smem;                       // padded input channel
    float* bufs = smem + SMW;                 // 2 x 3-row assembly buffers

    const int bc  = blockIdx.x;               // 0..2047
    const int tid = threadIdx.x;

    // ---- stage channel into padded smem (2 LDG.128 / thread) ----
    {
        const float4* __restrict__ s4 =
            reinterpret_cast<const float4*>(x + (size_t)bc * CH);
#pragma unroll
        for (int v = tid; v < CH / 4; v += NT) {
            float4 d = s4[v];
            int w = 4 * v;
            sin[PADI(w + 0)] = d.x;
            sin[PADI(w + 1)] = d.y;
            sin[PADI(w + 2)] = d.z;
            sin[PADI(w + 3)] = d.w;
        }
    }
    __syncthreads();

#pragma unroll
    for (int ki = 0; ki < 3; ++ki) {
        float*  rb  = bufs + (ki & 1) * GRPF;
        float4* rb4 = reinterpret_cast<float4*>(rb);

        if (ki >= 2) {                        // buffer reused by group ki-2:
            if (tid == 0)                     // let only group ki-1 stay live
                asm volatile("cp.async.bulk.wait_group 1;" ::: "memory");
            __syncthreads();
        }

        // ---- assemble rows 3ki+0..2 into rb (8 LDS + 6 SEL + 3 STS.128) ----
#pragma unroll
        for (int it = 0; it < 2; ++it) {      // 961 = 512 + 449
            const int m = tid + NT * it;
            if (m < NV4) {
                const int l   = 4 * m;
                const int i0  = l / WO;       // const divisor -> mulhi
                const int j0  = l - WO * i0;
                const int C   = ki * HW + l + 2 * i0;
                const bool cr = (j0 == 60);   // only e=2,3 cross (+2 words)

                const float s0 = sin[PADI(C + 0)];
                const float s1 = sin[PADI(C + 1)];
                const float s2 = sin[PADI(C + 2)];
                const float s3 = sin[PADI(C + 3)];
                const float s4 = sin[PADI(C + 4)];
                const float s5 = sin[PADI(C + 5)];
                const float s6 = sin[PADI(C + 6)];
                const float s7 = sin[PADI(C + 7)];

                float4 v;
                // kj = 0
                v.x = s0; v.y = s1;
                v.z = cr ? s4 : s2; v.w = cr ? s5 : s3;
                rb4[0 * NV4 + m] = v;
                // kj = 1
                v.x = s1; v.y = s2;
                v.z = cr ? s5 : s3; v.w = cr ? s6 : s4;
                rb4[1 * NV4 + m] = v;
                // kj = 2
                v.x = s2; v.y = s3;
                v.z = cr ? s6 : s4; v.w = cr ? s7 : s5;
                rb4[2 * NV4 + m] = v;
            }
        }
        __syncthreads();                      // assembly visible

        if (tid == 0) {
            asm volatile("fence.proxy.async.shared::cta;" ::: "memory");
            const uint32_t sbase = smem_u32(rb);
#pragma unroll
            for (int kj = 0; kj < 3; ++kj) {
                const float* g = out + ((size_t)bc * 9 + 3 * ki + kj) * L;
                asm volatile(
                    "cp.async.bulk.global.shared::cta.bulk_group [%0], [%1], %2;"
                    :: "l"(g), "r"(sbase + (uint32_t)kj * (L * 4)), "n"(L * 4)
                    : "memory");
            }
            asm volatile("cp.async.bulk.commit_group;" ::: "memory");
        }
    }

    // drain all bulk stores before smem deallocates at block exit
    if (tid == 0)
        asm volatile("cp.async.bulk.wait_group 0;" ::: "memory");
    __syncthreads();
}

extern "C" void kernel_launch(void* const* d_in, const int* in_sizes, int n_in,
                              void* d_out, int out_size)
{
    const float* x = (const float*)d_in[0];
    float* out = (float*)d_out;

    cudaFuncSetAttribute(unfold_kernel,
                         cudaFuncAttributeMaxDynamicSharedMemorySize, SMEMB);

    unfold_kernel<<<2048, NT, SMEMB>>>(x, out);   // one block per channel
}

// round 14
// speedup vs baseline: 1.0060x; 1.0060x over previous
#include <cuda_runtime.h>
#include <cstdint>

// Unfold (im2col): x[32,64,64,64] f32, 3x3/s1 -> out[32,576,3844] f32
// out[(bc*9+3ki+kj)][l+e] = ch[ki*64 + kj + (l+e) + 2*floor((l+e)/62)]
//
// R14 hybrid: padded-smem shared-window gather (8 LDS + 6 SEL per (m,ki));
// rows for ki=0,1 are assembled in smem and stored via cp.async.bulk (TMA,
// one group each, distinct buffers -> NO intra-loop waits); rows for ki=2
// are stored directly with st.global.cs (keeps LSU busy while the ki=1 TMA
// group drains, so the exit wait_group 0 is covered). Two store engines in
// parallel, zero pipeline stalls.

#define HW     64
#define CH     4096
#define WO     62
#define L      3844
#define NV4    961                 // float4 per output row
#define SMW    4240                // padded input: 4096 + pad + slack
#define NT     512
#define GRPF   (3 * L)             // floats per 3-row group buffer = 11532
#define SMEMB  ((SMW + 2 * GRPF) * 4)   // 109216 bytes

__device__ __forceinline__ int PADI(int w) { return w + (w >> 5); }

__device__ __forceinline__ uint32_t smem_u32(const void* p) {
    uint32_t a;
    asm("{ .reg .u64 t; cvta.to.shared.u64 t, %1; cvt.u32.u64 %0, t; }"
        : "=r"(a) : "l"(p));
    return a;
}

__device__ __forceinline__ void stcs4(float4* p, float4 v) {
    asm volatile("st.global.cs.v4.f32 [%0], {%1,%2,%3,%4};"
                 :: "l"(p), "f"(v.x), "f"(v.y), "f"(v.z), "f"(v.w)
                 : "memory");
}

__global__ __launch_bounds__(NT, 2)
void unfold_kernel(const float* __restrict__ x, float* __restrict__ out)
{
    extern __shared__ float smem[];
    float* sin  = smem;                       // padded input channel
    float* bufs = smem + SMW;                 // 2 x 3-row assembly buffers

    const int bc  = blockIdx.x;               // 0..2047
    const int tid = threadIdx.x;

    // ---- stage channel into padded smem (2 LDG.128 / thread) ----
    {
        const float4* __restrict__ s4 =
            reinterpret_cast<const float4*>(x + (size_t)bc * CH);
#pragma unroll
        for (int v = tid; v < CH / 4; v += NT) {
            float4 d = s4[v];
            int w = 4 * v;
            sin[PADI(w + 0)] = d.x;
            sin[PADI(w + 1)] = d.y;
            sin[PADI(w + 2)] = d.z;
            sin[PADI(w + 3)] = d.w;
        }
    }
    __syncthreads();

    float4* __restrict__ dst4 =
        reinterpret_cast<float4*>(out + (size_t)bc * 9 * L);

    // ---- ki = 0,1 : assemble 3 rows in smem, store via TMA bulk group ----
#pragma unroll
    for (int ki = 0; ki < 2; ++ki) {
        float4* rb4 = reinterpret_cast<float4*>(bufs + ki * GRPF);

#pragma unroll
        for (int it = 0; it < 2; ++it) {      // 961 = 512 + 449
            const int m = tid + NT * it;
            if (m < NV4) {
                const int l   = 4 * m;
                const int i0  = l / WO;       // const divisor -> mulhi
                const int j0  = l - WO * i0;
                const int C   = ki * HW + l + 2 * i0;
                const bool cr = (j0 == 60);   // only e=2,3 cross (+2 words)

                const float s0 = sin[PADI(C + 0)];
                const float s1 = sin[PADI(C + 1)];
                const float s2 = sin[PADI(C + 2)];
                const float s3 = sin[PADI(C + 3)];
                const float s4 = sin[PADI(C + 4)];
                const float s5 = sin[PADI(C + 5)];
                const float s6 = sin[PADI(C + 6)];
                const float s7 = sin[PADI(C + 7)];

                float4 v;
                v.x = s0; v.y = s1;
                v.z = cr ? s4 : s2; v.w = cr ? s5 : s3;
                rb4[0 * NV4 + m] = v;
                v.x = s1; v.y = s2;
                v.z = cr ? s5 : s3; v.w = cr ? s6 : s4;
                rb4[1 * NV4 + m] = v;
                v.x = s2; v.y = s3;
                v.z = cr ? s6 : s4; v.w = cr ? s7 : s5;
                rb4[2 * NV4 + m] = v;
            }
        }
        __syncthreads();                      // assembly visible to TMA

        if (tid == 0) {
            asm volatile("fence.proxy.async.shared::cta;" ::: "memory");
            const uint32_t sbase = smem_u32(bufs + ki * GRPF);
#pragma unroll
            for (int kj = 0; kj < 3; ++kj) {
                const float* g = out + ((size_t)bc * 9 + 3 * ki + kj) * L;
                asm volatile(
                    "cp.async.bulk.global.shared::cta.bulk_group [%0], [%1], %2;"
                    :: "l"(g), "r"(sbase + (uint32_t)kj * (L * 4)), "n"(L * 4)
                    : "memory");
            }
            asm volatile("cp.async.bulk.commit_group;" ::: "memory");
        }
    }

    // ---- ki = 2 : direct st.global.cs (covers the ki=1 TMA drain) ----
#pragma unroll
    for (int it = 0; it < 2; ++it) {
        const int m = tid + NT * it;
        if (m < NV4) {
            const int l   = 4 * m;
            const int i0  = l / WO;
            const int j0  = l - WO * i0;
            const int C   = 2 * HW + l + 2 * i0;
            const bool cr = (j0 == 60);

            const float s0 = sin[PADI(C + 0)];
            const float s1 = sin[PADI(C + 1)];
            const float s2 = sin[PADI(C + 2)];
            const float s3 = sin[PADI(C + 3)];
            const float s4 = sin[PADI(C + 4)];
            const float s5 = sin[PADI(C + 5)];
            const float s6 = sin[PADI(C + 6)];
            const float s7 = sin[PADI(C + 7)];

            float4 v;
            v.x = s0; v.y = s1;
            v.z = cr ? s4 : s2; v.w = cr ? s5 : s3;
            stcs4(&dst4[6 * NV4 + m], v);
            v.x = s1; v.y = s2;
            v.z = cr ? s5 : s3; v.w = cr ? s6 : s4;
            stcs4(&dst4[7 * NV4 + m], v);
            v.x = s2; v.y = s3;
            v.z = cr ? s6 : s4; v.w = cr ? s7 : s5;
            stcs4(&dst4[8 * NV4 + m], v);
        }
    }

    // drain TMA groups (normally already complete) before smem deallocates
    if (tid == 0)
        asm volatile("cp.async.bulk.wait_group 0;" ::: "memory");
    __syncthreads();
}

extern "C" void kernel_launch(void* const* d_in, const int* in_sizes, int n_in,
                              void* d_out, int out_size)
{
    const float* x = (const float*)d_in[0];
    float* out = (float*)d_out;

    cudaFuncSetAttribute(unfold_kernel,
                         cudaFuncAttributeMaxDynamicSharedMemorySize, SMEMB);

    unfold_kernel<<<2048, NT, SMEMB>>>(x, out);   // one block per channel
}

// round 15
// speedup vs baseline: 1.1197x; 1.1130x over previous
#include <cuda_runtime.h>
#include <cstdint>

// Unfold (im2col): x[32,64,64,64] f32, 3x3/s1 -> out[32,576,3844] f32
// out[(bc*9+3ki+kj)][l+e] = ch[ki*64 + kj + (l+e) + 2*floor((l+e)/62)]
//
// R15 = R14 hybrid (padded-smem shared-window gather; ki=0,1 rows assembled
// in smem and stored by TMA bulk groups, ki=2 stored direct with st.global.cs)
// + L2::evict_first cache policy on the TMA stores. R10's .cs stores won on
// bench despite slower ncu because evict_first keeps 283MB of streaming
// writes from accumulating as normal-priority dirty L2 lines across graph
// replays; default-policy TMA stores poisoned L2 for the NEXT replay. This
// gives the TMA path the same streaming semantics.

#define HW     64
#define CH     4096
#define WO     62
#define L      3844
#define NV4    961                 // float4 per output row
#define SMW    4240                // padded input: 4096 + pad + slack
#define NT     512
#define GRPF   (3 * L)             // floats per 3-row group buffer = 11532
#define SMEMB  ((SMW + 2 * GRPF) * 4)   // 109216 bytes

__device__ __forceinline__ int PADI(int w) { return w + (w >> 5); }

__device__ __forceinline__ uint32_t smem_u32(const void* p) {
    uint32_t a;
    asm("{ .reg .u64 t; cvta.to.shared.u64 t, %1; cvt.u32.u64 %0, t; }"
        : "=r"(a) : "l"(p));
    return a;
}

__device__ __forceinline__ void stcs4(float4* p, float4 v) {
    asm volatile("st.global.cs.v4.f32 [%0], {%1,%2,%3,%4};"
                 :: "l"(p), "f"(v.x), "f"(v.y), "f"(v.z), "f"(v.w)
                 : "memory");
}

__global__ __launch_bounds__(NT, 2)
void unfold_kernel(const float* __restrict__ x, float* __restrict__ out)
{
    extern __shared__ float smem[];
    float* sin  = smem;                       // padded input channel
    float* bufs = smem + SMW;                 // 2 x 3-row assembly buffers

    const int bc  = blockIdx.x;               // 0..2047
    const int tid = threadIdx.x;

    // streaming (evict_first) L2 policy for the bulk stores
    uint64_t pol;
    asm("createpolicy.fractional.L2::evict_first.b64 %0, 1.0;" : "=l"(pol));

    // ---- stage channel into padded smem (2 LDG.128 / thread) ----
    {
        const float4* __restrict__ s4 =
            reinterpret_cast<const float4*>(x + (size_t)bc * CH);
#pragma unroll
        for (int v = tid; v < CH / 4; v += NT) {
            float4 d = s4[v];
            int w = 4 * v;
            sin[PADI(w + 0)] = d.x;
            sin[PADI(w + 1)] = d.y;
            sin[PADI(w + 2)] = d.z;
            sin[PADI(w + 3)] = d.w;
        }
    }
    __syncthreads();

    float4* __restrict__ dst4 =
        reinterpret_cast<float4*>(out + (size_t)bc * 9 * L);

    // ---- ki = 0,1 : assemble 3 rows in smem, store via TMA bulk group ----
#pragma unroll
    for (int ki = 0; ki < 2; ++ki) {
        float4* rb4 = reinterpret_cast<float4*>(bufs + ki * GRPF);

#pragma unroll
        for (int it = 0; it < 2; ++it) {      // 961 = 512 + 449
            const int m = tid + NT * it;
            if (m < NV4) {
                const int l   = 4 * m;
                const int i0  = l / WO;       // const divisor -> mulhi
                const int j0  = l - WO * i0;
                const int C   = ki * HW + l + 2 * i0;
                const bool cr = (j0 == 60);   // only e=2,3 cross (+2 words)

                const float s0 = sin[PADI(C + 0)];
                const float s1 = sin[PADI(C + 1)];
                const float s2 = sin[PADI(C + 2)];
                const float s3 = sin[PADI(C + 3)];
                const float s4 = sin[PADI(C + 4)];
                const float s5 = sin[PADI(C + 5)];
                const float s6 = sin[PADI(C + 6)];
                const float s7 = sin[PADI(C + 7)];

                float4 v;
                v.x = s0; v.y = s1;
                v.z = cr ? s4 : s2; v.w = cr ? s5 : s3;
                rb4[0 * NV4 + m] = v;
                v.x = s1; v.y = s2;
                v.z = cr ? s5 : s3; v.w = cr ? s6 : s4;
                rb4[1 * NV4 + m] = v;
                v.x = s2; v.y = s3;
                v.z = cr ? s6 : s4; v.w = cr ? s7 : s5;
                rb4[2 * NV4 + m] = v;
            }
        }
        __syncthreads();                      // assembly visible to TMA

        if (tid == 0) {
            asm volatile("fence.proxy.async.shared::cta;" ::: "memory");
            const uint32_t sbase = smem_u32(bufs + ki * GRPF);
#pragma unroll
            for (int kj = 0; kj < 3; ++kj) {
                const float* g = out + ((size_t)bc * 9 + 3 * ki + kj) * L;
                asm volatile(
                    "cp.async.bulk.global.shared::cta.bulk_group.L2::cache_hint"
                    " [%0], [%1], %2, %3;"
                    :: "l"(g), "r"(sbase + (uint32_t)kj * (L * 4)), "n"(L * 4),
                       "l"(pol)
                    : "memory");
            }
            asm volatile("cp.async.bulk.commit_group;" ::: "memory");
        }
    }

    // ---- ki = 2 : direct st.global.cs (covers the ki=1 TMA drain) ----
#pragma unroll
    for (int it = 0; it < 2; ++it) {
        const int m = tid + NT * it;
        if (m < NV4) {
            const int l   = 4 * m;
            const int i0  = l / WO;
            const int j0  = l - WO * i0;
            const int C   = 2 * HW + l + 2 * i0;
            const bool cr = (j0 == 60);

            const float s0 = sin[PADI(C + 0)];
            const float s1 = sin[PADI(C + 1)];
            const float s2 = sin[PADI(C + 2)];
            const float s3 = sin[PADI(C + 3)];
            const float s4 = sin[PADI(C + 4)];
            const float s5 = sin[PADI(C + 5)];
            const float s6 = sin[PADI(C + 6)];
            const float s7 = sin[PADI(C + 7)];

            float4 v;
            v.x = s0; v.y = s1;
            v.z = cr ? s4 : s2; v.w = cr ? s5 : s3;
            stcs4(&dst4[6 * NV4 + m], v);
            v.x = s1; v.y = s2;
            v.z = cr ? s5 : s3; v.w = cr ? s6 : s4;
            stcs4(&dst4[7 * NV4 + m], v);
            v.x = s2; v.y = s3;
            v.z = cr ? s6 : s4; v.w = cr ? s7 : s5;
            stcs4(&dst4[8 * NV4 + m], v);
        }
    }

    // drain TMA groups (normally already complete) before smem deallocates
    if (tid == 0)
        asm volatile("cp.async.bulk.wait_group 0;" ::: "memory");
    __syncthreads();
}

extern "C" void kernel_launch(void* const* d_in, const int* in_sizes, int n_in,
                              void* d_out, int out_size)
{
    const float* x = (const float*)d_in[0];
    float* out = (float*)d_out;

    cudaFuncSetAttribute(unfold_kernel,
                         cudaFuncAttributeMaxDynamicSharedMemorySize, SMEMB);

    unfold_kernel<<<2048, NT, SMEMB>>>(x, out);   // one block per channel
}